// round 14
// baseline (speedup 1.0000x reference)
#include <cuda_runtime.h>
#include <cuda_bf16.h>
#include <cstdint>

// -------- problem constants --------
#define BB      512
#define TT      256
#define D_IN    64
#define D_STATE 64
#define NN      2048
#define D_OUT   10
#define KAUG    128

// -------- decomposition: 16 neuron-groups x 8 batch-groups = 128 CTAs ----
#define NG      16
#define BG      8
#define NT      128     // neurons per CTA (GEMM1 N, GEMM2 K)
#define BT      64      // batch rows per CTA (M)
#define NCTAS   128
#define THREADS 512

// -------- SMEM: bf16 row-major, stride 136 (68 words = 4 mod 32 -> CF) ----
#define KS      136
#define XA_HI   0
#define XA_LO   (XA_HI  + BT * KS)
#define E_HI    (XA_LO  + BT * KS)
#define E_LO    (E_HI   + NT * KS)
#define SDT_HI  (E_LO   + NT * KS)
#define SDT_LO  (SDT_HI + D_STATE * KS)
#define A2_HI   (SDT_LO + D_STATE * KS)
#define A2_LO   (A2_HI  + BT * KS)
#define SMEM_ELEMS (A2_LO + BT * KS)
#define SMEM_BYTES (SMEM_ELEMS * 2)

// -------- global scratch (static; no allocation) --------
// Per-timestep accumulated state: REDG targets. Zeroed per launch (bi-local).
__device__ float g_s[TT][BB][D_STATE];          // 33.5 MB
__device__ float g_ypart[NG][BB][D_OUT];

// per-bi barriers (padded); gen monotonic across graph replays
__device__ unsigned g_cntb[BG * 32];
__device__ volatile unsigned g_genb[BG * 32];

__device__ __forceinline__ void gsync_bi(int bi) {
    __syncthreads();
    if (threadIdx.x == 0) {
        __threadfence();
        unsigned gen = g_genb[bi * 32];            // read BEFORE arriving
        unsigned prev = atomicAdd(&g_cntb[bi * 32], 1);
        if (prev == NG - 1) {
            g_cntb[bi * 32] = 0;
            __threadfence();
            g_genb[bi * 32] = gen + 1;
        } else {
            while (g_genb[bi * 32] == gen) { }
            __threadfence();
        }
    }
    __syncthreads();
}

// -------- warp-level bf16 MMA (sm_80+ baseline PTX; no arch-a gating) -----
__device__ __forceinline__ void mma_bf16(float* c, uint32_t a0, uint32_t a1,
                                         uint32_t a2, uint32_t a3,
                                         uint32_t b0, uint32_t b1) {
    asm volatile(
        "mma.sync.aligned.m16n8k16.row.col.f32.bf16.bf16.f32 "
        "{%0,%1,%2,%3}, {%4,%5,%6,%7}, {%8,%9}, {%0,%1,%2,%3};"
        : "+f"(c[0]), "+f"(c[1]), "+f"(c[2]), "+f"(c[3])
        : "r"(a0), "r"(a1), "r"(a2), "r"(a3), "r"(b0), "r"(b1));
}

__device__ __forceinline__ void ldsm4(uint32_t addr, uint32_t* r) {
    asm volatile("ldmatrix.sync.aligned.m8n8.x4.shared.b16 {%0,%1,%2,%3}, [%4];"
        : "=r"(r[0]), "=r"(r[1]), "=r"(r[2]), "=r"(r[3]) : "r"(addr));
}

// vector RED: fire-and-forget float2 add to global (sm_90+ baseline PTX)
__device__ __forceinline__ void red2(float* addr, float x, float y) {
    asm volatile("red.global.add.v2.f32 [%0], {%1, %2};"
                 :: "l"(addr), "f"(x), "f"(y) : "memory");
}

// 3 split passes (hh + lh + hl) for one n8 column group
__device__ __forceinline__ void mma3(float* c, const uint32_t* ah, const uint32_t* al,
                                     uint32_t bh0, uint32_t bh1,
                                     uint32_t bl0, uint32_t bl1) {
    mma_bf16(c, ah[0], ah[1], ah[2], ah[3], bh0, bh1);   // hi*hi
    mma_bf16(c, al[0], al[1], al[2], al[3], bh0, bh1);   // lo*hi
    mma_bf16(c, ah[0], ah[1], ah[2], ah[3], bl0, bl1);   // hi*lo
}

// 3-pass split GEMM, 16x32 warp tile, K=128, ldmatrix fragment loads.
__device__ __forceinline__ void gemm3(const __nv_bfloat16* Ah, const __nv_bfloat16* Al,
                                      const __nv_bfloat16* Bh, const __nv_bfloat16* Bl,
                                      int m0, int n0, int lane,
                                      float acc[4][4]) {
    const int rowA = m0 + (lane & 15);
    const int colA = (lane >> 4) << 3;
    const int rowB = n0 + ((lane >> 4) << 3) + (lane & 7);
    const int colB = ((lane >> 3) & 1) << 3;

    uint32_t aH  = (uint32_t)__cvta_generic_to_shared(Ah + rowA * KS + colA);
    uint32_t aL  = (uint32_t)__cvta_generic_to_shared(Al + rowA * KS + colA);
    uint32_t bH0 = (uint32_t)__cvta_generic_to_shared(Bh + rowB * KS + colB);
    uint32_t bL0 = (uint32_t)__cvta_generic_to_shared(Bl + rowB * KS + colB);
    const uint32_t nstep = 16u * KS * 2u;          // +16 B-rows (bytes)

#pragma unroll
    for (int ks = 0; ks < 8; ks++) {
        const uint32_t o = (uint32_t)ks * 32u;     // 16 bf16 = 32B along k
        uint32_t ah[4], al[4], bh0[4], bh1[4], bl0[4], bl1[4];
        ldsm4(aH + o, ah);
        ldsm4(aL + o, al);
        ldsm4(bH0 + o, bh0);
        ldsm4(bH0 + nstep + o, bh1);
        ldsm4(bL0 + o, bl0);
        ldsm4(bL0 + nstep + o, bl1);
        mma3(acc[0], ah, al, bh0[0], bh0[1], bl0[0], bl0[1]);   // ns=0
        mma3(acc[1], ah, al, bh0[2], bh0[3], bl0[2], bl0[3]);   // ns=1
        mma3(acc[2], ah, al, bh1[0], bh1[1], bl1[0], bl1[1]);   // ns=2
        mma3(acc[3], ah, al, bh1[2], bh1[3], bl1[2], bl1[3]);   // ns=3
    }
}

// 3-pass split GEMM, 16x16 warp tile (one B n16-group), K=128.
__device__ __forceinline__ void gemm3h(const __nv_bfloat16* Ah, const __nv_bfloat16* Al,
                                       const __nv_bfloat16* Bh, const __nv_bfloat16* Bl,
                                       int m0, int n0, int lane,
                                       float acc[2][4]) {
    const int rowA = m0 + (lane & 15);
    const int colA = (lane >> 4) << 3;
    const int rowB = n0 + ((lane >> 4) << 3) + (lane & 7);
    const int colB = ((lane >> 3) & 1) << 3;

    uint32_t aH  = (uint32_t)__cvta_generic_to_shared(Ah + rowA * KS + colA);
    uint32_t aL  = (uint32_t)__cvta_generic_to_shared(Al + rowA * KS + colA);
    uint32_t bH0 = (uint32_t)__cvta_generic_to_shared(Bh + rowB * KS + colB);
    uint32_t bL0 = (uint32_t)__cvta_generic_to_shared(Bl + rowB * KS + colB);

#pragma unroll
    for (int ks = 0; ks < 8; ks++) {
        const uint32_t o = (uint32_t)ks * 32u;
        uint32_t ah[4], al[4], bh0[4], bl0[4];
        ldsm4(aH + o, ah);
        ldsm4(aL + o, al);
        ldsm4(bH0 + o, bh0);
        ldsm4(bL0 + o, bl0);
        mma3(acc[0], ah, al, bh0[0], bh0[1], bl0[0], bl0[1]);   // ns=0
        mma3(acc[1], ah, al, bh0[2], bh0[3], bl0[2], bl0[3]);   // ns=1
    }
}

// split two floats into bf16 hi/lo pairs and store packed (k-pair granularity)
__device__ __forceinline__ void split_pair_store(__nv_bfloat16* bh, __nv_bfloat16* bl,
                                                 int row, int kpair, float x, float y) {
    __nv_bfloat162 h, l;
    h.x = __float2bfloat16(x);
    h.y = __float2bfloat16(y);
    l.x = __float2bfloat16(x - __bfloat162float(h.x));
    l.y = __float2bfloat16(y - __bfloat162float(h.y));
    *(__nv_bfloat162*)(bh + row * KS + kpair * 2) = h;
    *(__nv_bfloat162*)(bl + row * KS + kpair * 2) = l;
}

__global__ void __launch_bounds__(THREADS, 1)
nef_kernel(const float* __restrict__ seq,     // [B][T][D_IN]
           const float* __restrict__ enc,     // [NN][KAUG]
           const float* __restrict__ bias,    // [NN]
           const float* __restrict__ gain,    // [NN]
           const float* __restrict__ sdec,    // [NN][D_STATE]
           const float* __restrict__ dec,     // [NN][D_OUT]
           float* __restrict__ out)           // [B][D_OUT]
{
    extern __shared__ __nv_bfloat16 smem[];
    __nv_bfloat16* XAh = smem + XA_HI;
    __nv_bfloat16* XAl = smem + XA_LO;
    __nv_bfloat16* Eh  = smem + E_HI;
    __nv_bfloat16* El  = smem + E_LO;
    __nv_bfloat16* SDh = smem + SDT_HI;
    __nv_bfloat16* SDl = smem + SDT_LO;
    __nv_bfloat16* A2h = smem + A2_HI;
    __nv_bfloat16* A2l = smem + A2_LO;

    const int tid  = threadIdx.x;
    const int wid  = tid >> 5;
    const int lane = tid & 31;
    const int g    = lane >> 2;          // groupID
    const int t4   = lane & 3;           // thread-in-group
    const int ni   = blockIdx.x & (NG - 1);
    const int bi   = blockIdx.x >> 4;
    const int nbase = ni * NT;
    const int bbase = bi * BT;

    // GEMM1 warp tile (16x32): m0a in {0,16,32,48}, n0a in {0,32,64,96}
    const int m0a = 16 * (wid & 3);
    const int n0a = 32 * (wid >> 2);
    // GEMM2 warp tile (16x16): all 16 warps cover 64x64
    const int m0b = 16 * (wid & 3);
    const int d0b = 16 * (wid >> 2);

    // ---- one-time weight staging (bf16 hi/lo) ----
    for (int i = tid; i < NT * (KAUG / 2); i += THREADS) {
        int n = i >> 6, p = i & 63;
        float2 v = *(const float2*)&enc[(nbase + n) * KAUG + 2 * p];
        split_pair_store(Eh, El, n, p, v.x, v.y);
    }
    for (int i = tid; i < D_STATE * (NT / 2); i += THREADS) {
        int d = i >> 6, p = i & 63;
        float x = sdec[(nbase + 2 * p) * D_STATE + d];
        float y = sdec[(nbase + 2 * p + 1) * D_STATE + d];
        split_pair_store(SDh, SDl, d, p, x, y);
    }
    // per-thread gain/bias for epilogue1 (columns n0a + 8ns + 2t4 (+1))
    float gj[4][2], bj[4][2];
#pragma unroll
    for (int ns = 0; ns < 4; ns++) {
        int n = nbase + n0a + 8 * ns + 2 * t4;
        gj[ns][0] = gain[n];     gj[ns][1] = gain[n + 1];
        bj[ns][0] = bias[n];     bj[ns][1] = bias[n + 1];
    }

    // ---- zero this bi-group's slice of g_s (bi-local coverage) ----
    // CTA (ni,bi) zeroes t in [ni*16, ni*16+16) for rows [bbase, bbase+64)
    {
        float4 z4 = make_float4(0.f, 0.f, 0.f, 0.f);
        for (int i = tid; i < 16 * BT * 16; i += THREADS) {   // 16384 float4
            int t  = ni * 16 + (i >> 10);
            int r  = (i >> 4) & 63;
            int dq = i & 15;
            *(float4*)&g_s[t][bbase + r][dq * 4] = z4;
        }
    }

    // ---- initial XA = [u(0) | 0] ----
    for (int i = tid; i < BT * (D_IN / 2); i += THREADS) {
        int r = i >> 5, p = i & 31;
        float2 v = *(const float2*)&seq[((size_t)(bbase + r) * TT) * D_IN + 2 * p];
        split_pair_store(XAh, XAl, r, p, v.x, v.y);
    }
    for (int i = tid; i < BT * (D_STATE / 2); i += THREADS) {
        int r = i >> 5, p = i & 31;
        split_pair_store(XAh, XAl, r, 32 + p, 0.f, 0.f);
    }
    gsync_bi(bi);   // g_s slice zeroed across the bi-group before any REDs

    for (int t = 0; t < TT; t++) {
        // ======== GEMM1: a = XA @ E^T (16 warps, 16x32 tiles) ========
        float acc[4][4];
#pragma unroll
        for (int ns = 0; ns < 4; ns++)
#pragma unroll
            for (int q = 0; q < 4; q++) acc[ns][q] = 0.f;

        gemm3(XAh, XAl, Eh, El, m0a, n0a, lane, acc);

        // ======== epilogue 1: act = |gain*v + bias| -> A2 hi/lo ========
#pragma unroll
        for (int ns = 0; ns < 4; ns++) {
            float v0 = fabsf(fmaf(gj[ns][0], acc[ns][0], bj[ns][0]));
            float v1 = fabsf(fmaf(gj[ns][1], acc[ns][1], bj[ns][1]));
            float v2 = fabsf(fmaf(gj[ns][0], acc[ns][2], bj[ns][0]));
            float v3 = fabsf(fmaf(gj[ns][1], acc[ns][3], bj[ns][1]));
            int r0 = m0a + g;
            int kp = (n0a + 8 * ns) / 2 + t4;
            split_pair_store(A2h, A2l, r0,     kp, v0, v1);
            split_pair_store(A2h, A2l, r0 + 8, kp, v2, v3);
        }

        if (t == TT - 1) break;

        __syncthreads();   // A2 visible to GEMM2 warps

        // ======== GEMM2: s_part = a @ SD (ALL 16 warps, 16x16 tiles) ====
        {
            float acc2[2][4];
#pragma unroll
            for (int ns = 0; ns < 2; ns++)
#pragma unroll
                for (int q = 0; q < 4; q++) acc2[ns][q] = 0.f;

            gemm3h(A2h, A2l, SDh, SDl, m0b, d0b, lane, acc2);

            // epilogue 2: vector REDs into per-timestep accumulator
#pragma unroll
            for (int ns = 0; ns < 2; ns++) {
                int r0 = m0b + g;
                int d  = d0b + 8 * ns + 2 * t4;
                red2(&g_s[t][bbase + r0][d],     acc2[ns][0], acc2[ns][1]);
                red2(&g_s[t][bbase + r0 + 8][d], acc2[ns][2], acc2[ns][3]);
            }
        }

        gsync_bi(bi);   // all 16 ni-sharers' REDs into g_s[t] are visible

        // ---- fill phase: prefetch u(t+1) (DRAM) + read s(t) (L2-hot),
        //      loads first (6 outstanding per thread), then stores ----
        {
            float2 uf[4];
#pragma unroll
            for (int q = 0; q < 4; q++) {
                int i = tid + THREADS * q;       // 0..2047
                int r = i >> 5, p = i & 31;
                uf[q] = *(const float2*)&seq[((size_t)(bbase + r) * TT + t + 1) * D_IN + 2 * p];
            }
            int r0 = tid >> 4, dq0 = tid & 15;               // item tid
            int r1 = (tid + THREADS) >> 4, dq1 = tid & 15;   // item tid+512
            float4 s0 = __ldcg((const float4*)&g_s[t][bbase + r0][dq0 * 4]);
            float4 s1 = __ldcg((const float4*)&g_s[t][bbase + r1][dq1 * 4]);

#pragma unroll
            for (int q = 0; q < 4; q++) {
                int i = tid + THREADS * q;
                int r = i >> 5, p = i & 31;
                split_pair_store(XAh, XAl, r, p, uf[q].x, uf[q].y);
            }
            split_pair_store(XAh, XAl, r0, 32 + 2 * dq0,     s0.x, s0.y);
            split_pair_store(XAh, XAl, r0, 32 + 2 * dq0 + 1, s0.z, s0.w);
            split_pair_store(XAh, XAl, r1, 32 + 2 * dq1,     s1.x, s1.y);
            split_pair_store(XAh, XAl, r1, 32 + 2 * dq1 + 1, s1.z, s1.w);
        }
        __syncthreads();
    }

    // ======== final decode: y = a @ dec ========
    __syncthreads();
    for (int idx = tid; idx < BT * D_OUT; idx += THREADS) {
        int b = idx / D_OUT, o = idx - b * D_OUT;
        float s = 0.f;
#pragma unroll 4
        for (int n = 0; n < NT; n++) {
            float a = __bfloat162float(A2h[b * KS + n]) + __bfloat162float(A2l[b * KS + n]);
            s += a * dec[(nbase + n) * D_OUT + o];
        }
        g_ypart[ni][bbase + b][o] = s;
    }
    gsync_bi(bi);

    if (ni == 0) {
        for (int idx = tid; idx < BT * D_OUT; idx += THREADS) {
            int b = idx / D_OUT, o = idx - b * D_OUT;
            float s = 0.f;
#pragma unroll
            for (int gg = 0; gg < NG; gg++)
                s += g_ypart[gg][bbase + b][o];
            out[(bbase + b) * D_OUT + o] = s;
        }
    }
}

extern "C" void kernel_launch(void* const* d_in, const int* in_sizes, int n_in,
                              void* d_out, int out_size) {
    (void)in_sizes; (void)n_in; (void)out_size;
    cudaFuncSetAttribute(nef_kernel, cudaFuncAttributeMaxDynamicSharedMemorySize,
                         SMEM_BYTES);
    nef_kernel<<<NCTAS, THREADS, SMEM_BYTES>>>(
        (const float*)d_in[0],   // seq
        (const float*)d_in[1],   // encoders
        (const float*)d_in[2],   // bias
        (const float*)d_in[3],   // gain
        (const float*)d_in[4],   // state_decoders
        (const float*)d_in[5],   // decoders
        (float*)d_out);
}

// round 15
// speedup vs baseline: 1.5978x; 1.5978x over previous
#include <cuda_runtime.h>
#include <cuda_bf16.h>
#include <cstdint>

// -------- problem constants --------
#define BB      512
#define TT      256
#define D_IN    64
#define D_STATE 64
#define NN      2048
#define D_OUT   10
#define KAUG    128

// -------- decomposition: 16 neuron-groups x 8 batch-groups = 128 CTAs ----
#define NG      16
#define BG      8
#define NT      128     // neurons per CTA (GEMM1 N, GEMM2 K)
#define BT      64      // batch rows per CTA (M)
#define NCTAS   128
#define THREADS 512

// -------- SMEM: bf16 row-major, stride 136 (68 words = 4 mod 32 -> CF) ----
#define KS      136
#define XA_HI   0
#define XA_LO   (XA_HI  + BT * KS)
#define E_HI    (XA_LO  + BT * KS)
#define E_LO    (E_HI   + NT * KS)
#define SDT_HI  (E_LO   + NT * KS)
#define SDT_LO  (SDT_HI + D_STATE * KS)
#define A2_HI   (SDT_LO + D_STATE * KS)
#define A2_LO   (A2_HI  + BT * KS)
#define SMEM_ELEMS (A2_LO + BT * KS)
#define SMEM_BYTES (SMEM_ELEMS * 2)

// -------- global scratch (static; no allocation) --------
// Per-timestep accumulated state: REDG targets. Zeroed per launch (bi-local).
__device__ float g_s[TT][BB][D_STATE];          // 33.5 MB
__device__ float g_ypart[NG][BB][D_OUT];

// per-bi barriers (padded); gen monotonic across graph replays
__device__ unsigned g_cntb[BG * 32];
__device__ volatile unsigned g_genb[BG * 32];

__device__ __forceinline__ void gsync_bi(int bi) {
    __syncthreads();
    if (threadIdx.x == 0) {
        __threadfence();
        unsigned gen = g_genb[bi * 32];            // read BEFORE arriving
        unsigned prev = atomicAdd(&g_cntb[bi * 32], 1);
        if (prev == NG - 1) {
            g_cntb[bi * 32] = 0;
            __threadfence();
            g_genb[bi * 32] = gen + 1;
        } else {
            while (g_genb[bi * 32] == gen) { }
            __threadfence();
        }
    }
    __syncthreads();
}

// -------- warp-level bf16 MMA (sm_80+ baseline PTX; no arch-a gating) -----
__device__ __forceinline__ void mma_bf16(float* c, uint32_t a0, uint32_t a1,
                                         uint32_t a2, uint32_t a3,
                                         uint32_t b0, uint32_t b1) {
    asm volatile(
        "mma.sync.aligned.m16n8k16.row.col.f32.bf16.bf16.f32 "
        "{%0,%1,%2,%3}, {%4,%5,%6,%7}, {%8,%9}, {%0,%1,%2,%3};"
        : "+f"(c[0]), "+f"(c[1]), "+f"(c[2]), "+f"(c[3])
        : "r"(a0), "r"(a1), "r"(a2), "r"(a3), "r"(b0), "r"(b1));
}

__device__ __forceinline__ void ldsm4(uint32_t addr, uint32_t* r) {
    asm volatile("ldmatrix.sync.aligned.m8n8.x4.shared.b16 {%0,%1,%2,%3}, [%4];"
        : "=r"(r[0]), "=r"(r[1]), "=r"(r[2]), "=r"(r[3]) : "r"(addr));
}

// vector RED: fire-and-forget float2 add to global (sm_90+ baseline PTX)
__device__ __forceinline__ void red2(float* addr, float x, float y) {
    asm volatile("red.global.add.v2.f32 [%0], {%1, %2};"
                 :: "l"(addr), "f"(x), "f"(y) : "memory");
}

// 3 split passes (hh + lh + hl) for one n8 column group
__device__ __forceinline__ void mma3(float* c, const uint32_t* ah, const uint32_t* al,
                                     uint32_t bh0, uint32_t bh1,
                                     uint32_t bl0, uint32_t bl1) {
    mma_bf16(c, ah[0], ah[1], ah[2], ah[3], bh0, bh1);   // hi*hi
    mma_bf16(c, al[0], al[1], al[2], al[3], bh0, bh1);   // lo*hi
    mma_bf16(c, ah[0], ah[1], ah[2], ah[3], bl0, bl1);   // hi*lo
}

// 3-pass split GEMM, 16x32 warp tile, K=128, ldmatrix fragment loads.
// A=[rows][K] hi/lo, B=[cols][K] hi/lo, both KS-strided bf16 in SMEM.
__device__ __forceinline__ void gemm3(const __nv_bfloat16* Ah, const __nv_bfloat16* Al,
                                      const __nv_bfloat16* Bh, const __nv_bfloat16* Bl,
                                      int m0, int n0, int lane,
                                      float acc[4][4]) {
    const int rowA = m0 + (lane & 15);
    const int colA = (lane >> 4) << 3;
    const int rowB = n0 + ((lane >> 4) << 3) + (lane & 7);
    const int colB = ((lane >> 3) & 1) << 3;

    uint32_t aH  = (uint32_t)__cvta_generic_to_shared(Ah + rowA * KS + colA);
    uint32_t aL  = (uint32_t)__cvta_generic_to_shared(Al + rowA * KS + colA);
    uint32_t bH0 = (uint32_t)__cvta_generic_to_shared(Bh + rowB * KS + colB);
    uint32_t bL0 = (uint32_t)__cvta_generic_to_shared(Bl + rowB * KS + colB);
    const uint32_t nstep = 16u * KS * 2u;          // +16 B-rows (bytes)

#pragma unroll
    for (int ks = 0; ks < 8; ks++) {
        const uint32_t o = (uint32_t)ks * 32u;     // 16 bf16 = 32B along k
        uint32_t ah[4], al[4], bh0[4], bh1[4], bl0[4], bl1[4];
        ldsm4(aH + o, ah);
        ldsm4(aL + o, al);
        ldsm4(bH0 + o, bh0);
        ldsm4(bH0 + nstep + o, bh1);
        ldsm4(bL0 + o, bl0);
        ldsm4(bL0 + nstep + o, bl1);
        mma3(acc[0], ah, al, bh0[0], bh0[1], bl0[0], bl0[1]);   // ns=0
        mma3(acc[1], ah, al, bh0[2], bh0[3], bl0[2], bl0[3]);   // ns=1
        mma3(acc[2], ah, al, bh1[0], bh1[1], bl1[0], bl1[1]);   // ns=2
        mma3(acc[3], ah, al, bh1[2], bh1[3], bl1[2], bl1[3]);   // ns=3
    }
}

// split two floats into bf16 hi/lo pairs and store packed (k-pair granularity)
__device__ __forceinline__ void split_pair_store(__nv_bfloat16* bh, __nv_bfloat16* bl,
                                                 int row, int kpair, float x, float y) {
    __nv_bfloat162 h, l;
    h.x = __float2bfloat16(x);
    h.y = __float2bfloat16(y);
    l.x = __float2bfloat16(x - __bfloat162float(h.x));
    l.y = __float2bfloat16(y - __bfloat162float(h.y));
    *(__nv_bfloat162*)(bh + row * KS + kpair * 2) = h;
    *(__nv_bfloat162*)(bl + row * KS + kpair * 2) = l;
}

__global__ void __launch_bounds__(THREADS, 1)
nef_kernel(const float* __restrict__ seq,     // [B][T][D_IN]
           const float* __restrict__ enc,     // [NN][KAUG]
           const float* __restrict__ bias,    // [NN]
           const float* __restrict__ gain,    // [NN]
           const float* __restrict__ sdec,    // [NN][D_STATE]
           const float* __restrict__ dec,     // [NN][D_OUT]
           float* __restrict__ out)           // [B][D_OUT]
{
    extern __shared__ __nv_bfloat16 smem[];
    __nv_bfloat16* XAh = smem + XA_HI;
    __nv_bfloat16* XAl = smem + XA_LO;
    __nv_bfloat16* Eh  = smem + E_HI;
    __nv_bfloat16* El  = smem + E_LO;
    __nv_bfloat16* SDh = smem + SDT_HI;
    __nv_bfloat16* SDl = smem + SDT_LO;
    __nv_bfloat16* A2h = smem + A2_HI;
    __nv_bfloat16* A2l = smem + A2_LO;

    const int tid  = threadIdx.x;
    const int wid  = tid >> 5;
    const int lane = tid & 31;
    const int g    = lane >> 2;          // groupID
    const int t4   = lane & 3;           // thread-in-group
    const int ni   = blockIdx.x & (NG - 1);
    const int bi   = blockIdx.x >> 4;
    const int nbase = ni * NT;
    const int bbase = bi * BT;

    // GEMM1 warp tile (16x32): m0a in {0,16,32,48}, n0a in {0,32,64,96}
    const int m0a = 16 * (wid & 3);
    const int n0a = 32 * (wid >> 2);

    // ---- one-time weight staging (bf16 hi/lo) ----
    for (int i = tid; i < NT * (KAUG / 2); i += THREADS) {
        int n = i >> 6, p = i & 63;
        float2 v = *(const float2*)&enc[(nbase + n) * KAUG + 2 * p];
        split_pair_store(Eh, El, n, p, v.x, v.y);
    }
    for (int i = tid; i < D_STATE * (NT / 2); i += THREADS) {
        int d = i >> 6, p = i & 63;
        float x = sdec[(nbase + 2 * p) * D_STATE + d];
        float y = sdec[(nbase + 2 * p + 1) * D_STATE + d];
        split_pair_store(SDh, SDl, d, p, x, y);
    }
    // per-thread gain/bias for epilogue1 (columns n0a + 8ns + 2t4 (+1))
    float gj[4][2], bj[4][2];
#pragma unroll
    for (int ns = 0; ns < 4; ns++) {
        int n = nbase + n0a + 8 * ns + 2 * t4;
        gj[ns][0] = gain[n];     gj[ns][1] = gain[n + 1];
        bj[ns][0] = bias[n];     bj[ns][1] = bias[n + 1];
    }

    // ---- zero this bi-group's slice of g_s (bi-local coverage) ----
    // CTA (ni,bi) zeroes t in [ni*16, ni*16+16) for rows [bbase, bbase+64)
    {
        float4 z4 = make_float4(0.f, 0.f, 0.f, 0.f);
        for (int i = tid; i < 16 * BT * 16; i += THREADS) {   // 16384 float4
            int t  = ni * 16 + (i >> 10);
            int r  = (i >> 4) & 63;
            int dq = i & 15;
            *(float4*)&g_s[t][bbase + r][dq * 4] = z4;
        }
    }

    // ---- initial XA = [u(0) | 0] ----
    for (int i = tid; i < BT * (D_IN / 2); i += THREADS) {
        int r = i >> 5, p = i & 31;
        float2 v = *(const float2*)&seq[((size_t)(bbase + r) * TT) * D_IN + 2 * p];
        split_pair_store(XAh, XAl, r, p, v.x, v.y);
    }
    for (int i = tid; i < BT * (D_STATE / 2); i += THREADS) {
        int r = i >> 5, p = i & 31;
        split_pair_store(XAh, XAl, r, 32 + p, 0.f, 0.f);
    }
    gsync_bi(bi);   // g_s slice zeroed across the bi-group before any REDs

    for (int t = 0; t < TT; t++) {
        // ======== GEMM1: a = XA @ E^T (16 warps, 16x32 tiles) ========
        float acc[4][4];
#pragma unroll
        for (int ns = 0; ns < 4; ns++)
#pragma unroll
            for (int q = 0; q < 4; q++) acc[ns][q] = 0.f;

        gemm3(XAh, XAl, Eh, El, m0a, n0a, lane, acc);

        // ======== epilogue 1: act = |gain*v + bias| -> A2 hi/lo ========
#pragma unroll
        for (int ns = 0; ns < 4; ns++) {
            float v0 = fabsf(fmaf(gj[ns][0], acc[ns][0], bj[ns][0]));
            float v1 = fabsf(fmaf(gj[ns][1], acc[ns][1], bj[ns][1]));
            float v2 = fabsf(fmaf(gj[ns][0], acc[ns][2], bj[ns][0]));
            float v3 = fabsf(fmaf(gj[ns][1], acc[ns][3], bj[ns][1]));
            int r0 = m0a + g;
            int kp = (n0a + 8 * ns) / 2 + t4;
            split_pair_store(A2h, A2l, r0,     kp, v0, v1);
            split_pair_store(A2h, A2l, r0 + 8, kp, v2, v3);
        }

        if (t == TT - 1) break;

        __syncthreads();   // A2 visible to GEMM2 warps

        if (wid < 8) {
            // ======== GEMM2: s_part = a @ SD (warps 0-7, 16x32 tiles) ====
            const int m0b = 16 * (wid & 3);
            const int d0b = 32 * (wid >> 2);
            float acc2[4][4];
#pragma unroll
            for (int ns = 0; ns < 4; ns++)
#pragma unroll
                for (int q = 0; q < 4; q++) acc2[ns][q] = 0.f;

            gemm3(A2h, A2l, SDh, SDl, m0b, d0b, lane, acc2);

            // epilogue 2: vector REDs into per-timestep accumulator
#pragma unroll
            for (int ns = 0; ns < 4; ns++) {
                int r0 = m0b + g;
                int d  = d0b + 8 * ns + 2 * t4;
                red2(&g_s[t][bbase + r0][d],     acc2[ns][0], acc2[ns][1]);
                red2(&g_s[t][bbase + r0 + 8][d], acc2[ns][2], acc2[ns][3]);
            }
        } else {
            // ---- concurrent prefetch: u(t+1) -> XA u-part ----
            for (int i = tid - 256; i < BT * (D_IN / 2); i += 256) {
                int r = i >> 5, p = i & 31;
                float2 v = *(const float2*)&seq[((size_t)(bbase + r) * TT + t + 1) * D_IN + 2 * p];
                split_pair_store(XAh, XAl, r, p, v.x, v.y);
            }
        }

        gsync_bi(bi);   // all 16 ni-sharers' REDs into g_s[t] are visible

        // ---- state fill: read accumulated s(t) (16 KB, L2-hot) -> XA ----
#pragma unroll
        for (int j = 0; j < 2; j++) {
            int item = tid + THREADS * j;        // 0..1023
            int r  = item >> 4;                  // 0..63
            int dq = item & 15;                  // float4 block within d
            float4 s = __ldcg((const float4*)&g_s[t][bbase + r][dq * 4]);
            split_pair_store(XAh, XAl, r, 32 + 2 * dq,     s.x, s.y);
            split_pair_store(XAh, XAl, r, 32 + 2 * dq + 1, s.z, s.w);
        }
        __syncthreads();
    }

    // ======== final decode: y = a @ dec ========
    __syncthreads();
    for (int idx = tid; idx < BT * D_OUT; idx += THREADS) {
        int b = idx / D_OUT, o = idx - b * D_OUT;
        float s = 0.f;
#pragma unroll 4
        for (int n = 0; n < NT; n++) {
            float a = __bfloat162float(A2h[b * KS + n]) + __bfloat162float(A2l[b * KS + n]);
            s += a * dec[(nbase + n) * D_OUT + o];
        }
        g_ypart[ni][bbase + b][o] = s;
    }
    gsync_bi(bi);

    if (ni == 0) {
        for (int idx = tid; idx < BT * D_OUT; idx += THREADS) {
            int b = idx / D_OUT, o = idx - b * D_OUT;
            float s = 0.f;
#pragma unroll
            for (int gg = 0; gg < NG; gg++)
                s += g_ypart[gg][bbase + b][o];
            out[(bbase + b) * D_OUT + o] = s;
        }
    }
}

extern "C" void kernel_launch(void* const* d_in, const int* in_sizes, int n_in,
                              void* d_out, int out_size) {
    (void)in_sizes; (void)n_in; (void)out_size;
    cudaFuncSetAttribute(nef_kernel, cudaFuncAttributeMaxDynamicSharedMemorySize,
                         SMEM_BYTES);
    nef_kernel<<<NCTAS, THREADS, SMEM_BYTES>>>(
        (const float*)d_in[0],   // seq
        (const float*)d_in[1],   // encoders
        (const float*)d_in[2],   // bias
        (const float*)d_in[3],   // gain
        (const float*)d_in[4],   // state_decoders
        (const float*)d_in[5],   // decoders
        (float*)d_out);
}